// round 1
// baseline (speedup 1.0000x reference)
#include <cuda_runtime.h>
#include <math.h>

#define TT   2048
#define HH   2048
#define NHH  16
#define NOPE 128
#define ROPED 64
#define DQK  192     // NOPE + ROPE
#define VDIM 128
#define QLAT 1536
#define KVLAT 512
#define NE   8
#define MIDIM 512
#define SHI  1024    // 2*MI

// ---------------------------------------------------------------------------
// Scratch (static device memory; no allocations anywhere)
// ---------------------------------------------------------------------------
struct Scratch {
    float x1[TT * HH];
    float n1[TT * HH];
    float qa_pre[TT * QLAT];
    float qa[TT * QLAT];
    float q[TT * NHH * DQK];            // [T, 16, 192] (rope applied in place)
    float kv[TT * (KVLAT + ROPED)];     // [T, 576]
    float ckv[TT * KVLAT];
    float knope[TT * NHH * NOPE];
    float kfull[TT * NHH * DQK];        // [T, 16, 192]
    float v[TT * NHH * VDIM];           // [T, 2048]
    float S[(long long)NHH * TT * TT];  // 256 MB scores/probs
    float o[TT * NHH * VDIM];
    float attn[TT * HH];
    float x2[TT * HH];
    float n2[TT * HH];
    float h[TT * 2 * MIDIM];            // moe up output (per expert, reused)
    float ha[TT * MIDIM];
    float routed2[2 * TT * HH];         // slot0 / slot1 contributions
    float hs[TT * 2 * SHI];
    float hsa[TT * SHI];
    float shared_o[TT * HH];
    float ew[NE * TT];
    int   tok[NE * TT];
    int   orow[NE * TT];
    int   counts[NE];
};
__device__ Scratch g_s;

// ---------------------------------------------------------------------------
// Generic SGEMM: C[M,N] = scale * A[M,K] * op(B)
//   TRANSB=1 : B is [N,K] row-major  (x @ W^T)
//   TRANSB=0 : B is [K,N] row-major  (P @ V)
// Options: batch strides via blockIdx.z, causal tile skip, per-tile k-limit,
//          A row gather, device-side M, C row scatter with per-row scale.
// ---------------------------------------------------------------------------
template <bool TRANSB>
__global__ __launch_bounds__(256)
void gemm_k(const float* __restrict__ A, const float* __restrict__ B,
            float* __restrict__ C,
            int M, int N, int K, int lda, int ldb, int ldc,
            long long sA, long long sB, long long sC,
            float scale, int causal, int klim,
            const int* __restrict__ aidx, const int* __restrict__ mdev,
            const int* __restrict__ cidx, const float* __restrict__ cscale)
{
    A += (long long)blockIdx.z * sA;
    B += (long long)blockIdx.z * sB;
    C += (long long)blockIdx.z * sC;
    const int Meff = mdev ? *mdev : M;
    const int m0 = blockIdx.y * 128;
    const int n0 = blockIdx.x * 128;
    if (m0 >= Meff) return;
    if (causal && n0 > m0 + 127) return;
    const int kmax = klim ? min(K, m0 + 128) : K;

    __shared__ float As[16][128];
    __shared__ float Bs[16][128];

    const int tid = threadIdx.x;
    const int tx = tid & 15;
    const int ty = tid >> 4;

    float acc[8][8];
#pragma unroll
    for (int i = 0; i < 8; i++)
#pragma unroll
        for (int j = 0; j < 8; j++) acc[i][j] = 0.f;

    for (int kt = 0; kt < kmax; kt += 16) {
        // --- load A tile (128 rows x 16 k), store transposed As[k][m]
#pragma unroll
        for (int i = 0; i < 2; i++) {
            int idx = tid + i * 256;           // 0..511
            int row = idx >> 2;
            int kq  = (idx & 3) << 2;
            float4 val = make_float4(0.f, 0.f, 0.f, 0.f);
            int gm = m0 + row;
            if (gm < Meff) {
                int ar = aidx ? aidx[gm] : gm;
                val = *reinterpret_cast<const float4*>(A + (long long)ar * lda + kt + kq);
            }
            As[kq + 0][row] = val.x;
            As[kq + 1][row] = val.y;
            As[kq + 2][row] = val.z;
            As[kq + 3][row] = val.w;
        }
        // --- load B tile
        if (TRANSB) {
#pragma unroll
            for (int i = 0; i < 2; i++) {
                int idx = tid + i * 256;
                int row = idx >> 2;
                int kq  = (idx & 3) << 2;
                float4 val = make_float4(0.f, 0.f, 0.f, 0.f);
                int gn = n0 + row;
                if (gn < N)
                    val = *reinterpret_cast<const float4*>(B + (long long)gn * ldb + kt + kq);
                Bs[kq + 0][row] = val.x;
                Bs[kq + 1][row] = val.y;
                Bs[kq + 2][row] = val.z;
                Bs[kq + 3][row] = val.w;
            }
        } else {
#pragma unroll
            for (int i = 0; i < 2; i++) {
                int idx = tid + i * 256;
                int kr = idx >> 5;
                int nq = (idx & 31) << 2;
                float4 val = make_float4(0.f, 0.f, 0.f, 0.f);
                int gn = n0 + nq;
                if (gn < N)
                    val = *reinterpret_cast<const float4*>(B + (long long)(kt + kr) * ldb + gn);
                *reinterpret_cast<float4*>(&Bs[kr][nq]) = val;
            }
        }
        __syncthreads();

#pragma unroll
        for (int kk = 0; kk < 16; kk++) {
            float a[8], b[8];
            *(float4*)&a[0] = *(float4*)&As[kk][ty * 8];
            *(float4*)&a[4] = *(float4*)&As[kk][ty * 8 + 4];
            *(float4*)&b[0] = *(float4*)&Bs[kk][tx * 8];
            *(float4*)&b[4] = *(float4*)&Bs[kk][tx * 8 + 4];
#pragma unroll
            for (int i = 0; i < 8; i++)
#pragma unroll
                for (int j = 0; j < 8; j++) acc[i][j] += a[i] * b[j];
        }
        __syncthreads();
    }

    // --- epilogue
#pragma unroll
    for (int i = 0; i < 8; i++) {
        int gm = m0 + ty * 8 + i;
        if (gm >= Meff) continue;
        long long crow = gm;
        float w = scale;
        if (cidx) { crow = cidx[gm]; w = scale * cscale[gm]; }
        float* cp = C + crow * (long long)ldc;
#pragma unroll
        for (int j = 0; j < 8; j++) {
            int gn = n0 + tx * 8 + j;
            if (gn < N) cp[gn] = acc[i][j] * w;
        }
    }
}

// ---------------------------------------------------------------------------
// Elementwise / reduction kernels
// ---------------------------------------------------------------------------
__global__ void zero_counts_k() {
    if (threadIdx.x < NE) g_s.counts[threadIdx.x] = 0;
}

__global__ void add2_k(const float* __restrict__ a, const float* __restrict__ b,
                       float* __restrict__ c, int n) {
    for (int i = blockIdx.x * blockDim.x + threadIdx.x; i < n; i += gridDim.x * blockDim.x)
        c[i] = a[i] + b[i];
}

__global__ void x2_out_k(const float* __restrict__ x1, const float* __restrict__ attn,
                         float* __restrict__ x2, float* __restrict__ dout, int n) {
    for (int i = blockIdx.x * blockDim.x + threadIdx.x; i < n; i += gridDim.x * blockDim.x) {
        float v = x1[i] + attn[i];
        x2[i] = v;
        dout[i] = v;
    }
}

__global__ void combine_k(const float* __restrict__ routed2, const float* __restrict__ sh,
                          float* __restrict__ dout, int n) {
    for (int i = blockIdx.x * blockDim.x + threadIdx.x; i < n; i += gridDim.x * blockDim.x)
        dout[i] = routed2[i] + routed2[n + i] + sh[i];
}

__global__ __launch_bounds__(256)
void rmsnorm_k(const float* __restrict__ in, const float* __restrict__ w,
               float* __restrict__ out, int cols, int instride, int outstride) {
    int row = blockIdx.x;
    const float* ip = in + (long long)row * instride;
    float ss = 0.f;
    for (int j = threadIdx.x; j < cols; j += 256) { float v = ip[j]; ss += v * v; }
    __shared__ float red[256];
    red[threadIdx.x] = ss;
    __syncthreads();
    for (int st = 128; st > 0; st >>= 1) {
        if (threadIdx.x < st) red[threadIdx.x] += red[threadIdx.x + st];
        __syncthreads();
    }
    float scale = rsqrtf(red[0] / (float)cols + 1e-6f);
    float* op = out + (long long)row * outstride;
    for (int j = threadIdx.x; j < cols; j += 256) op[j] = ip[j] * scale * w[j];
}

__global__ void rope_q_k(float* __restrict__ q, const float* __restrict__ rsin,
                         const float* __restrict__ rcos) {
    int t = blockIdx.x;
    for (int i = threadIdx.x; i < NHH * 32; i += blockDim.x) {
        int h = i >> 5;
        int p = i & 31;
        float* base = q + (long long)t * (NHH * DQK) + h * DQK + NOPE + 2 * p;
        float s = rsin[t * 32 + p], c = rcos[t * 32 + p];
        float a = base[0], b = base[1];
        base[0] = a * c - b * s;
        base[1] = a * s + b * c;
    }
}

__global__ void build_k_k(const float* __restrict__ knope, const float* __restrict__ kv,
                          const float* __restrict__ rsin, const float* __restrict__ rcos,
                          float* __restrict__ kfull) {
    int t = blockIdx.x;
    __shared__ float pe[ROPED];
    if (threadIdx.x < 32) {
        int p = threadIdx.x;
        float a = kv[(long long)t * (KVLAT + ROPED) + KVLAT + 2 * p];
        float b = kv[(long long)t * (KVLAT + ROPED) + KVLAT + 2 * p + 1];
        float s = rsin[t * 32 + p], c = rcos[t * 32 + p];
        pe[2 * p]     = a * c - b * s;
        pe[2 * p + 1] = a * s + b * c;
    }
    __syncthreads();
    for (int i = threadIdx.x; i < NHH * DQK; i += blockDim.x) {
        int h = i / DQK;
        int d = i % DQK;
        kfull[(long long)t * (NHH * DQK) + i] =
            (d < NOPE) ? knope[(long long)t * (NHH * NOPE) + h * NOPE + d] : pe[d - NOPE];
    }
}

__global__ __launch_bounds__(256)
void softmax_causal_k() {
    int qrow = blockIdx.x;
    int h = blockIdx.y;
    float* row = g_s.S + ((long long)h * TT + qrow) * TT;
    int len = qrow + 1;
    __shared__ float red[256];

    float m = -1e30f;
    for (int k = threadIdx.x; k < len; k += 256) m = fmaxf(m, row[k]);
    red[threadIdx.x] = m;
    __syncthreads();
    for (int st = 128; st > 0; st >>= 1) {
        if (threadIdx.x < st) red[threadIdx.x] = fmaxf(red[threadIdx.x], red[threadIdx.x + st]);
        __syncthreads();
    }
    m = red[0];
    __syncthreads();

    float s = 0.f;
    for (int k = threadIdx.x; k < len; k += 256) {
        float e = __expf(row[k] - m);
        row[k] = e;
        s += e;
    }
    red[threadIdx.x] = s;
    __syncthreads();
    for (int st = 128; st > 0; st >>= 1) {
        if (threadIdx.x < st) red[threadIdx.x] += red[threadIdx.x + st];
        __syncthreads();
    }
    float inv = 1.0f / red[0];
    for (int k = threadIdx.x; k < len; k += 256) row[k] *= inv;
    for (int k = len + threadIdx.x; k < TT; k += 256) row[k] = 0.f;
}

__global__ __launch_bounds__(256)
void gate_topk_k(const float* __restrict__ n2, const float* __restrict__ gw) {
    int t = blockIdx.x;
    __shared__ float logits[NE];
    int warp = threadIdx.x >> 5, lane = threadIdx.x & 31;
    const float* xp = n2 + (long long)t * HH;
    const float* wp = gw + warp * HH;
    float s = 0.f;
    for (int k = lane; k < HH; k += 32) s += xp[k] * wp[k];
    for (int off = 16; off > 0; off >>= 1) s += __shfl_down_sync(0xffffffffu, s, off);
    if (lane == 0) logits[warp] = s;
    __syncthreads();
    if (threadIdx.x == 0) {
        float m = logits[0];
        for (int e = 1; e < NE; e++) m = fmaxf(m, logits[e]);
        float p[NE];
        float sum = 0.f;
        for (int e = 0; e < NE; e++) { p[e] = __expf(logits[e] - m); sum += p[e]; }
        for (int e = 0; e < NE; e++) p[e] /= sum;
        int i0 = 0;
        for (int e = 1; e < NE; e++) if (p[e] > p[i0]) i0 = e;
        int i1 = -1;
        for (int e = 0; e < NE; e++) {
            if (e == i0) continue;
            if (i1 < 0 || p[e] > p[i1]) i1 = e;
        }
        float w0 = p[i0], w1 = p[i1];
        float tot = w0 + w1;
        w0 /= tot; w1 /= tot;   // MOE_SCALE = 1
        int pos0 = atomicAdd(&g_s.counts[i0], 1);
        g_s.tok[i0 * TT + pos0] = t;
        g_s.orow[i0 * TT + pos0] = t;            // slot 0
        g_s.ew[i0 * TT + pos0] = w0;
        int pos1 = atomicAdd(&g_s.counts[i1], 1);
        g_s.tok[i1 * TT + pos1] = t;
        g_s.orow[i1 * TT + pos1] = TT + t;       // slot 1
        g_s.ew[i1 * TT + pos1] = w1;
    }
}

__global__ void silu_gate_k(const float* __restrict__ in, float* __restrict__ out,
                            int half, const int* __restrict__ mdev, int Mmax) {
    int Meff = mdev ? *mdev : Mmax;
    int row = blockIdx.x;
    if (row >= Meff) return;
    const float* ip = in + (long long)row * 2 * half;
    float* op = out + (long long)row * half;
    for (int j = threadIdx.x; j < half; j += blockDim.x) {
        float a = ip[j], b = ip[half + j];
        op[j] = (a / (1.f + __expf(-a))) * b;
    }
}

// ---------------------------------------------------------------------------
// Host-side launch helpers
// ---------------------------------------------------------------------------
static void launch_gemm(bool transb, const float* A, const float* B, float* C,
                        int M, int N, int K, int lda, int ldb, int ldc,
                        long long sA, long long sB, long long sC, int bz,
                        float sc, int causal, int klim,
                        const int* aidx, const int* mdev,
                        const int* cidx, const float* cs)
{
    dim3 grid((N + 127) / 128, (M + 127) / 128, bz);
    if (transb)
        gemm_k<true><<<grid, 256>>>(A, B, C, M, N, K, lda, ldb, ldc, sA, sB, sC,
                                    sc, causal, klim, aidx, mdev, cidx, cs);
    else
        gemm_k<false><<<grid, 256>>>(A, B, C, M, N, K, lda, ldb, ldc, sA, sB, sC,
                                     sc, causal, klim, aidx, mdev, cidx, cs);
}

static void launch_nt(const float* A, const float* B, float* C, int M, int N, int K,
                      int lda, int ldb, int ldc)
{
    launch_gemm(true, A, B, C, M, N, K, lda, ldb, ldc, 0, 0, 0, 1, 1.f, 0, 0,
                nullptr, nullptr, nullptr, nullptr);
}

// ---------------------------------------------------------------------------
extern "C" void kernel_launch(void* const* d_in, const int* in_sizes, int n_in,
                              void* d_out, int out_size)
{
    const float* x    = (const float*)d_in[0];
    const float* skip = (const float*)d_in[1];
    const float* rsin = (const float*)d_in[2];
    const float* rcos = (const float*)d_in[3];
    const float* ln1  = (const float*)d_in[4];
    const float* ln2  = (const float*)d_in[5];
    const float* wqa  = (const float*)d_in[6];
    const float* qan  = (const float*)d_in[7];
    const float* wqb  = (const float*)d_in[8];
    const float* wkva = (const float*)d_in[9];
    const float* kvan = (const float*)d_in[10];
    const float* wkb  = (const float*)d_in[11];
    const float* wvb  = (const float*)d_in[12];
    const float* wo   = (const float*)d_in[13];
    const float* gw   = (const float*)d_in[14];
    const float* wup  = (const float*)d_in[15];
    const float* wdn  = (const float*)d_in[16];
    const float* wsup = (const float*)d_in[17];
    const float* wsdn = (const float*)d_in[18];
    float* out = (float*)d_out;

    Scratch* s = nullptr;
    cudaGetSymbolAddress((void**)&s, g_s);

    const int n = TT * HH;

    zero_counts_k<<<1, 32>>>();

    // x1 = x + skip ; n1 = rms(x1) * ln1
    add2_k<<<4096, 256>>>(x, skip, s->x1, n);
    rmsnorm_k<<<TT, 256>>>(s->x1, ln1, s->n1, HH, HH, HH);

    // qa = rms(n1 @ w_qa^T) ; q = qa @ w_qb^T ; rope
    launch_nt(s->n1, wqa, s->qa_pre, TT, QLAT, HH, HH, HH, QLAT);
    rmsnorm_k<<<TT, 256>>>(s->qa_pre, qan, s->qa, QLAT, QLAT, QLAT);
    launch_nt(s->qa, wqb, s->q, TT, NHH * DQK, QLAT, QLAT, QLAT, NHH * DQK);
    rope_q_k<<<TT, 256>>>(s->q, rsin, rcos);

    // kv path
    launch_nt(s->n1, wkva, s->kv, TT, KVLAT + ROPED, HH, HH, HH, KVLAT + ROPED);
    rmsnorm_k<<<TT, 256>>>(s->kv, kvan, s->ckv, KVLAT, KVLAT + ROPED, KVLAT);
    launch_nt(s->ckv, wkb, s->knope, TT, NHH * NOPE, KVLAT, KVLAT, KVLAT, NHH * NOPE);
    build_k_k<<<TT, 256>>>(s->knope, s->kv, rsin, rcos, s->kfull);
    launch_nt(s->ckv, wvb, s->v, TT, NHH * VDIM, KVLAT, KVLAT, KVLAT, NHH * VDIM);

    // attention: S = scale * Q K^T (causal), softmax, O = P V
    float attn_scale = 1.0f / sqrtf((float)DQK);
    launch_gemm(true, s->q, s->kfull, s->S, TT, TT, DQK,
                NHH * DQK, NHH * DQK, TT,
                DQK, DQK, (long long)TT * TT, NHH,
                attn_scale, /*causal=*/1, 0, nullptr, nullptr, nullptr, nullptr);
    softmax_causal_k<<<dim3(TT, NHH), 256>>>();
    launch_gemm(false, s->S, s->v, s->o, TT, VDIM, TT,
                TT, NHH * VDIM, NHH * VDIM,
                (long long)TT * TT, VDIM, VDIM, NHH,
                1.f, 0, /*klim=*/1, nullptr, nullptr, nullptr, nullptr);

    // attn out + residual -> x2 (output part 1)
    launch_nt(s->o, wo, s->attn, TT, HH, NHH * VDIM, NHH * VDIM, NHH * VDIM, HH);
    x2_out_k<<<4096, 256>>>(s->x1, s->attn, s->x2, out, n);

    // n2 and MoE gating
    rmsnorm_k<<<TT, 256>>>(s->x2, ln2, s->n2, HH, HH, HH);
    gate_topk_k<<<TT, 256>>>(s->n2, gw);

    // shared FFN
    launch_nt(s->n2, wsup, s->hs, TT, 2 * SHI, HH, HH, HH, 2 * SHI);
    silu_gate_k<<<TT, 256>>>(s->hs, s->hsa, SHI, nullptr, TT);
    launch_nt(s->hsa, wsdn, s->shared_o, TT, HH, SHI, SHI, SHI, HH);

    // routed experts (sparse: gather rows, variable M, scatter with weight)
    for (int e = 0; e < NE; e++) {
        const float* up = wup + (long long)e * (2 * MIDIM) * HH;
        const float* dn = wdn + (long long)e * HH * MIDIM;
        launch_gemm(true, s->n2, up, s->h, TT, 2 * MIDIM, HH,
                    HH, HH, 2 * MIDIM, 0, 0, 0, 1, 1.f, 0, 0,
                    s->tok + e * TT, s->counts + e, nullptr, nullptr);
        silu_gate_k<<<TT, 256>>>(s->h, s->ha, MIDIM, s->counts + e, TT);
        launch_gemm(true, s->ha, dn, s->routed2, TT, HH, MIDIM,
                    MIDIM, MIDIM, HH, 0, 0, 0, 1, 1.f, 0, 0,
                    nullptr, s->counts + e, s->orow + e * TT, s->ew + e * TT);
    }

    // ffn = routed(slot0) + routed(slot1) + shared  (output part 2)
    combine_k<<<4096, 256>>>(s->routed2, s->shared_o, out + (long long)n, n);
}

// round 2
// speedup vs baseline: 2.5263x; 2.5263x over previous
#include <cuda_runtime.h>
#include <math.h>

#define TT   2048
#define HH   2048
#define NHH  16
#define NOPE 128
#define ROPED 64
#define DQK  192     // NOPE + ROPE
#define VDIM 128
#define QLAT 1536
#define KVLAT 512
#define NE   8
#define MIDIM 512
#define SHI  1024    // 2*MI

// ---------------------------------------------------------------------------
// Scratch (static device memory; no allocations anywhere)
// ---------------------------------------------------------------------------
struct Scratch {
    float x1[TT * HH];
    float n1[TT * HH];
    float qa_pre[TT * QLAT];
    float qa[TT * QLAT];
    float q[TT * NHH * DQK];            // [T, 16, 192] (rope applied in place)
    float kv[TT * (KVLAT + ROPED)];     // [T, 576]
    float ckv[TT * KVLAT];
    float knope[TT * NHH * NOPE];
    float kfull[TT * NHH * DQK];        // [T, 16, 192]
    float v[TT * NHH * VDIM];           // [T, 2048]
    float S[(long long)NHH * TT * TT];  // 256 MB scores/probs
    float o[TT * NHH * VDIM];
    float attn[TT * HH];
    float x2[TT * HH];
    float n2[TT * HH];
    float h[(long long)NE * TT * 2 * MIDIM];   // per-expert up output
    float ha[(long long)NE * TT * MIDIM];      // per-expert activated
    float routed2[2 * TT * HH];         // slot0 / slot1 contributions
    float hs[TT * 2 * SHI];
    float hsa[TT * SHI];
    float shared_o[TT * HH];
    float ew[NE * TT];
    int   tok[NE * TT];
    int   orow[NE * TT];
    int   counts[NE];
};
__device__ Scratch g_s;

// ---------------------------------------------------------------------------
// tf32 helpers
// ---------------------------------------------------------------------------
__device__ __forceinline__ unsigned f2tf32(float x) {
    unsigned y;
    asm("cvt.rna.tf32.f32 %0, %1;" : "=r"(y) : "f"(x));
    return y;
}

__device__ __forceinline__ void mma_tf32(float* d, const unsigned* a, const unsigned* b) {
    asm volatile(
        "mma.sync.aligned.m16n8k8.row.col.f32.tf32.tf32.f32 "
        "{%0,%1,%2,%3}, {%4,%5,%6,%7}, {%8,%9}, {%0,%1,%2,%3};\n"
        : "+f"(d[0]), "+f"(d[1]), "+f"(d[2]), "+f"(d[3])
        : "r"(a[0]), "r"(a[1]), "r"(a[2]), "r"(a[3]), "r"(b[0]), "r"(b[1]));
}

// ---------------------------------------------------------------------------
// Tensor-core tf32 GEMM: C[M,N] = scale * A[M,K] * op(B)
//   TRANSB=1 : B is [N,K] row-major  (x @ W^T)
//   TRANSB=0 : B is [K,N] row-major  (P @ V)
// Block tile 128x128x32, 8 warps, warp tile 32x64.
// Smem: k-major, XOR swizzle col^(((k>>2)&7)<<2), width 136 -> conflict-free
// stores AND fragment loads.
// pstride: MoE batching — per-blockIdx.z mdev/aidx/cidx/cscale offsets.
// ---------------------------------------------------------------------------
template <bool TRANSB>
__global__ __launch_bounds__(256)
void gemm_tc(const float* __restrict__ A, const float* __restrict__ B,
             float* __restrict__ C,
             int M, int N, int K, int lda, int ldb, int ldc,
             long long sA, long long sB, long long sC,
             float scale, int causal, int klim,
             const int* __restrict__ aidx, const int* __restrict__ mdev,
             const int* __restrict__ cidx, const float* __restrict__ cscale,
             int pstride)
{
    const int z = blockIdx.z;
    A += (long long)z * sA;
    B += (long long)z * sB;
    C += (long long)z * sC;
    if (pstride) {
        if (mdev)   mdev   += z;
        if (aidx)   aidx   += (long long)z * pstride;
        if (cidx)   cidx   += (long long)z * pstride;
        if (cscale) cscale += (long long)z * pstride;
    }
    const int Meff = mdev ? *mdev : M;
    const int m0 = blockIdx.y * 128;
    const int n0 = blockIdx.x * 128;
    if (m0 >= Meff) return;
    if (causal && n0 > m0 + 127) return;
    const int kmax = klim ? min(K, m0 + 128) : K;

    __shared__ unsigned As[32][136];
    __shared__ unsigned Bs[32][136];

    const int tid = threadIdx.x;
    const int lane = tid & 31;
    const int wid = tid >> 5;
    const int wm = (wid & 3) * 32;   // warp m offset
    const int wn = (wid >> 2) * 64;  // warp n offset
    const int lm = lane & 3;         // k low
    const int lr = lane >> 2;        // 0..7

    float acc[2][8][4];
#pragma unroll
    for (int i = 0; i < 2; i++)
#pragma unroll
        for (int j = 0; j < 8; j++)
#pragma unroll
            for (int c = 0; c < 4; c++) acc[i][j][c] = 0.f;

    float4 ra[4], rb[4];

    auto loadA = [&](int kt) {
#pragma unroll
        for (int i = 0; i < 4; i++) {
            int idx = tid + i * 256;
            int row = idx >> 3;
            int kq  = (idx & 7) << 2;
            ra[i] = make_float4(0.f, 0.f, 0.f, 0.f);
            int gm = m0 + row;
            if (gm < Meff) {
                int ar = aidx ? aidx[gm] : gm;
                ra[i] = *reinterpret_cast<const float4*>(A + (long long)ar * lda + kt + kq);
            }
        }
    };
    auto storeA = [&]() {
#pragma unroll
        for (int i = 0; i < 4; i++) {
            int idx = tid + i * 256;
            int row = idx >> 3;
            int kq  = (idx & 7) << 2;
            int col = row ^ ((((kq >> 2) & 7)) << 2);
            As[kq + 0][col] = f2tf32(ra[i].x);
            As[kq + 1][col] = f2tf32(ra[i].y);
            As[kq + 2][col] = f2tf32(ra[i].z);
            As[kq + 3][col] = f2tf32(ra[i].w);
        }
    };
    auto loadB = [&](int kt) {
#pragma unroll
        for (int i = 0; i < 4; i++) {
            int idx = tid + i * 256;
            rb[i] = make_float4(0.f, 0.f, 0.f, 0.f);
            if (TRANSB) {
                int row = idx >> 3;
                int kq  = (idx & 7) << 2;
                int gn = n0 + row;
                if (gn < N)
                    rb[i] = *reinterpret_cast<const float4*>(B + (long long)gn * ldb + kt + kq);
            } else {
                int kr = idx >> 5;
                int nq = (idx & 31) << 2;
                int gn = n0 + nq;
                if (gn < N)
                    rb[i] = *reinterpret_cast<const float4*>(B + (long long)(kt + kr) * ldb + gn);
            }
        }
    };
    auto storeB = [&]() {
#pragma unroll
        for (int i = 0; i < 4; i++) {
            int idx = tid + i * 256;
            if (TRANSB) {
                int row = idx >> 3;
                int kq  = (idx & 7) << 2;
                int col = row ^ ((((kq >> 2) & 7)) << 2);
                Bs[kq + 0][col] = f2tf32(rb[i].x);
                Bs[kq + 1][col] = f2tf32(rb[i].y);
                Bs[kq + 2][col] = f2tf32(rb[i].z);
                Bs[kq + 3][col] = f2tf32(rb[i].w);
            } else {
                int kr = idx >> 5;
                int nq = (idx & 31) << 2;
                int col = nq ^ ((((kr >> 2) & 7)) << 2);
                Bs[kr][col + 0] = f2tf32(rb[i].x);
                Bs[kr][col + 1] = f2tf32(rb[i].y);
                Bs[kr][col + 2] = f2tf32(rb[i].z);
                Bs[kr][col + 3] = f2tf32(rb[i].w);
            }
        }
    };

    auto compute = [&]() {
#pragma unroll
        for (int kk8 = 0; kk8 < 4; kk8++) {
            const int k0 = kk8 * 8 + lm;
            const unsigned c0 = ((2 * kk8) & 7) << 2;
            const unsigned c1 = ((2 * kk8 + 1) & 7) << 2;
            unsigned afr[2][4], bfr[8][2];
#pragma unroll
            for (int im = 0; im < 2; im++) {
                int m = wm + im * 16 + lr;
                afr[im][0] = As[k0][m ^ c0];
                afr[im][1] = As[k0][(m + 8) ^ c0];
                afr[im][2] = As[k0 + 4][m ^ c1];
                afr[im][3] = As[k0 + 4][(m + 8) ^ c1];
            }
#pragma unroll
            for (int jn = 0; jn < 8; jn++) {
                int nn = wn + jn * 8 + lr;
                bfr[jn][0] = Bs[k0][nn ^ c0];
                bfr[jn][1] = Bs[k0 + 4][nn ^ c1];
            }
#pragma unroll
            for (int im = 0; im < 2; im++)
#pragma unroll
                for (int jn = 0; jn < 8; jn++)
                    mma_tf32(acc[im][jn], afr[im], bfr[jn]);
        }
    };

    // pipeline: prefetch next tile's globals into regs during compute
    loadA(0);
    loadB(0);
    storeA();
    storeB();
    __syncthreads();

    for (int kt = 0; kt < kmax; kt += 32) {
        bool has_next = (kt + 32) < kmax;
        if (has_next) { loadA(kt + 32); loadB(kt + 32); }
        compute();
        if (has_next) {
            __syncthreads();
            storeA();
            storeB();
        }
        __syncthreads();
    }

    // epilogue
#pragma unroll
    for (int im = 0; im < 2; im++) {
#pragma unroll
        for (int part = 0; part < 2; part++) {
            int gm = m0 + wm + im * 16 + lr + part * 8;
            if (gm >= Meff) continue;
            long long crow = gm;
            float w = scale;
            if (cidx) { crow = cidx[gm]; w = scale * cscale[gm]; }
            float* cp = C + crow * (long long)ldc;
#pragma unroll
            for (int jn = 0; jn < 8; jn++) {
                int gn = n0 + wn + jn * 8 + lm * 2;
                if (gn < N) {
                    float2 v2 = make_float2(acc[im][jn][part * 2] * w,
                                            acc[im][jn][part * 2 + 1] * w);
                    *reinterpret_cast<float2*>(cp + gn) = v2;
                }
            }
        }
    }
}

// ---------------------------------------------------------------------------
// Elementwise / reduction kernels
// ---------------------------------------------------------------------------
__global__ void zero_counts_k() {
    if (threadIdx.x < NE) g_s.counts[threadIdx.x] = 0;
}

__global__ void add2_k(const float* __restrict__ a, const float* __restrict__ b,
                       float* __restrict__ c, int n) {
    for (int i = blockIdx.x * blockDim.x + threadIdx.x; i < n; i += gridDim.x * blockDim.x)
        c[i] = a[i] + b[i];
}

__global__ void x2_out_k(const float* __restrict__ x1, const float* __restrict__ attn,
                         float* __restrict__ x2, float* __restrict__ dout, int n) {
    for (int i = blockIdx.x * blockDim.x + threadIdx.x; i < n; i += gridDim.x * blockDim.x) {
        float v = x1[i] + attn[i];
        x2[i] = v;
        dout[i] = v;
    }
}

__global__ void combine_k(const float* __restrict__ routed2, const float* __restrict__ sh,
                          float* __restrict__ dout, int n) {
    for (int i = blockIdx.x * blockDim.x + threadIdx.x; i < n; i += gridDim.x * blockDim.x)
        dout[i] = routed2[i] + routed2[n + i] + sh[i];
}

__global__ __launch_bounds__(256)
void rmsnorm_k(const float* __restrict__ in, const float* __restrict__ w,
               float* __restrict__ out, int cols, int instride, int outstride) {
    int row = blockIdx.x;
    const float* ip = in + (long long)row * instride;
    float ss = 0.f;
    for (int j = threadIdx.x; j < cols; j += 256) { float v = ip[j]; ss += v * v; }
    __shared__ float red[256];
    red[threadIdx.x] = ss;
    __syncthreads();
    for (int st = 128; st > 0; st >>= 1) {
        if (threadIdx.x < st) red[threadIdx.x] += red[threadIdx.x + st];
        __syncthreads();
    }
    float scale = rsqrtf(red[0] / (float)cols + 1e-6f);
    float* op = out + (long long)row * outstride;
    for (int j = threadIdx.x; j < cols; j += 256) op[j] = ip[j] * scale * w[j];
}

__global__ void rope_q_k(float* __restrict__ q, const float* __restrict__ rsin,
                         const float* __restrict__ rcos) {
    int t = blockIdx.x;
    for (int i = threadIdx.x; i < NHH * 32; i += blockDim.x) {
        int h = i >> 5;
        int p = i & 31;
        float* base = q + (long long)t * (NHH * DQK) + h * DQK + NOPE + 2 * p;
        float s = rsin[t * 32 + p], c = rcos[t * 32 + p];
        float a = base[0], b = base[1];
        base[0] = a * c - b * s;
        base[1] = a * s + b * c;
    }
}

__global__ void build_k_k(const float* __restrict__ knope, const float* __restrict__ kv,
                          const float* __restrict__ rsin, const float* __restrict__ rcos,
                          float* __restrict__ kfull) {
    int t = blockIdx.x;
    __shared__ float pe[ROPED];
    if (threadIdx.x < 32) {
        int p = threadIdx.x;
        float a = kv[(long long)t * (KVLAT + ROPED) + KVLAT + 2 * p];
        float b = kv[(long long)t * (KVLAT + ROPED) + KVLAT + 2 * p + 1];
        float s = rsin[t * 32 + p], c = rcos[t * 32 + p];
        pe[2 * p]     = a * c - b * s;
        pe[2 * p + 1] = a * s + b * c;
    }
    __syncthreads();
    for (int i = threadIdx.x; i < NHH * DQK; i += blockDim.x) {
        int h = i / DQK;
        int d = i % DQK;
        kfull[(long long)t * (NHH * DQK) + i] =
            (d < NOPE) ? knope[(long long)t * (NHH * NOPE) + h * NOPE + d] : pe[d - NOPE];
    }
}

__global__ __launch_bounds__(256)
void softmax_causal_k() {
    int qrow = blockIdx.x;
    int h = blockIdx.y;
    float* row = g_s.S + ((long long)h * TT + qrow) * TT;
    int len = qrow + 1;
    __shared__ float red[256];

    float m = -1e30f;
    for (int k = threadIdx.x; k < len; k += 256) m = fmaxf(m, row[k]);
    red[threadIdx.x] = m;
    __syncthreads();
    for (int st = 128; st > 0; st >>= 1) {
        if (threadIdx.x < st) red[threadIdx.x] = fmaxf(red[threadIdx.x], red[threadIdx.x + st]);
        __syncthreads();
    }
    m = red[0];
    __syncthreads();

    float s = 0.f;
    for (int k = threadIdx.x; k < len; k += 256) {
        float e = __expf(row[k] - m);
        row[k] = e;
        s += e;
    }
    red[threadIdx.x] = s;
    __syncthreads();
    for (int st = 128; st > 0; st >>= 1) {
        if (threadIdx.x < st) red[threadIdx.x] += red[threadIdx.x + st];
        __syncthreads();
    }
    float inv = 1.0f / red[0];
    for (int k = threadIdx.x; k < len; k += 256) row[k] *= inv;
    for (int k = len + threadIdx.x; k < TT; k += 256) row[k] = 0.f;
}

__global__ __launch_bounds__(256)
void gate_topk_k(const float* __restrict__ n2, const float* __restrict__ gw) {
    int t = blockIdx.x;
    __shared__ float logits[NE];
    int warp = threadIdx.x >> 5, lane = threadIdx.x & 31;
    const float* xp = n2 + (long long)t * HH;
    const float* wp = gw + warp * HH;
    float s = 0.f;
    for (int k = lane; k < HH; k += 32) s += xp[k] * wp[k];
    for (int off = 16; off > 0; off >>= 1) s += __shfl_down_sync(0xffffffffu, s, off);
    if (lane == 0) logits[warp] = s;
    __syncthreads();
    if (threadIdx.x == 0) {
        float m = logits[0];
        for (int e = 1; e < NE; e++) m = fmaxf(m, logits[e]);
        float p[NE];
        float sum = 0.f;
        for (int e = 0; e < NE; e++) { p[e] = __expf(logits[e] - m); sum += p[e]; }
        for (int e = 0; e < NE; e++) p[e] /= sum;
        int i0 = 0;
        for (int e = 1; e < NE; e++) if (p[e] > p[i0]) i0 = e;
        int i1 = -1;
        for (int e = 0; e < NE; e++) {
            if (e == i0) continue;
            if (i1 < 0 || p[e] > p[i1]) i1 = e;
        }
        float w0 = p[i0], w1 = p[i1];
        float tot = w0 + w1;
        w0 /= tot; w1 /= tot;   // MOE_SCALE = 1
        int pos0 = atomicAdd(&g_s.counts[i0], 1);
        g_s.tok[i0 * TT + pos0] = t;
        g_s.orow[i0 * TT + pos0] = t;            // slot 0
        g_s.ew[i0 * TT + pos0] = w0;
        int pos1 = atomicAdd(&g_s.counts[i1], 1);
        g_s.tok[i1 * TT + pos1] = t;
        g_s.orow[i1 * TT + pos1] = TT + t;       // slot 1
        g_s.ew[i1 * TT + pos1] = w1;
    }
}

// shared-FFN silu (single tensor)
__global__ void silu_gate_k(const float* __restrict__ in, float* __restrict__ out,
                            int half) {
    int row = blockIdx.x;
    const float* ip = in + (long long)row * 2 * half;
    float* op = out + (long long)row * half;
    for (int j = threadIdx.x; j < half; j += blockDim.x) {
        float a = ip[j], b = ip[half + j];
        op[j] = (a / (1.f + __expf(-a))) * b;
    }
}

// batched per-expert silu: blockIdx.y = expert
__global__ void silu_gate_moe_k() {
    int e = blockIdx.y;
    int row = blockIdx.x;
    if (row >= g_s.counts[e]) return;
    const float* ip = g_s.h + ((long long)e * TT + row) * (2 * MIDIM);
    float* op = g_s.ha + ((long long)e * TT + row) * MIDIM;
    for (int j = threadIdx.x; j < MIDIM; j += blockDim.x) {
        float a = ip[j], b = ip[MIDIM + j];
        op[j] = (a / (1.f + __expf(-a))) * b;
    }
}

// ---------------------------------------------------------------------------
// Host-side launch helpers
// ---------------------------------------------------------------------------
static void launch_gemm(bool transb, const float* A, const float* B, float* C,
                        int M, int N, int K, int lda, int ldb, int ldc,
                        long long sA, long long sB, long long sC, int bz,
                        float sc, int causal, int klim,
                        const int* aidx, const int* mdev,
                        const int* cidx, const float* cs, int pstride)
{
    dim3 grid((N + 127) / 128, (M + 127) / 128, bz);
    if (transb)
        gemm_tc<true><<<grid, 256>>>(A, B, C, M, N, K, lda, ldb, ldc, sA, sB, sC,
                                     sc, causal, klim, aidx, mdev, cidx, cs, pstride);
    else
        gemm_tc<false><<<grid, 256>>>(A, B, C, M, N, K, lda, ldb, ldc, sA, sB, sC,
                                      sc, causal, klim, aidx, mdev, cidx, cs, pstride);
}

static void launch_nt(const float* A, const float* B, float* C, int M, int N, int K,
                      int lda, int ldb, int ldc)
{
    launch_gemm(true, A, B, C, M, N, K, lda, ldb, ldc, 0, 0, 0, 1, 1.f, 0, 0,
                nullptr, nullptr, nullptr, nullptr, 0);
}

// ---------------------------------------------------------------------------
extern "C" void kernel_launch(void* const* d_in, const int* in_sizes, int n_in,
                              void* d_out, int out_size)
{
    const float* x    = (const float*)d_in[0];
    const float* skip = (const float*)d_in[1];
    const float* rsin = (const float*)d_in[2];
    const float* rcos = (const float*)d_in[3];
    const float* ln1  = (const float*)d_in[4];
    const float* ln2  = (const float*)d_in[5];
    const float* wqa  = (const float*)d_in[6];
    const float* qan  = (const float*)d_in[7];
    const float* wqb  = (const float*)d_in[8];
    const float* wkva = (const float*)d_in[9];
    const float* kvan = (const float*)d_in[10];
    const float* wkb  = (const float*)d_in[11];
    const float* wvb  = (const float*)d_in[12];
    const float* wo   = (const float*)d_in[13];
    const float* gw   = (const float*)d_in[14];
    const float* wup  = (const float*)d_in[15];
    const float* wdn  = (const float*)d_in[16];
    const float* wsup = (const float*)d_in[17];
    const float* wsdn = (const float*)d_in[18];
    float* out = (float*)d_out;

    Scratch* s = nullptr;
    cudaGetSymbolAddress((void**)&s, g_s);

    const int n = TT * HH;

    zero_counts_k<<<1, 32>>>();

    // x1 = x + skip ; n1 = rms(x1) * ln1
    add2_k<<<4096, 256>>>(x, skip, s->x1, n);
    rmsnorm_k<<<TT, 256>>>(s->x1, ln1, s->n1, HH, HH, HH);

    // qa = rms(n1 @ w_qa^T) ; q = qa @ w_qb^T ; rope
    launch_nt(s->n1, wqa, s->qa_pre, TT, QLAT, HH, HH, HH, QLAT);
    rmsnorm_k<<<TT, 256>>>(s->qa_pre, qan, s->qa, QLAT, QLAT, QLAT);
    launch_nt(s->qa, wqb, s->q, TT, NHH * DQK, QLAT, QLAT, QLAT, NHH * DQK);
    rope_q_k<<<TT, 256>>>(s->q, rsin, rcos);

    // kv path
    launch_nt(s->n1, wkva, s->kv, TT, KVLAT + ROPED, HH, HH, HH, KVLAT + ROPED);
    rmsnorm_k<<<TT, 256>>>(s->kv, kvan, s->ckv, KVLAT, KVLAT + ROPED, KVLAT);
    launch_nt(s->ckv, wkb, s->knope, TT, NHH * NOPE, KVLAT, KVLAT, KVLAT, NHH * NOPE);
    build_k_k<<<TT, 256>>>(s->knope, s->kv, rsin, rcos, s->kfull);
    launch_nt(s->ckv, wvb, s->v, TT, NHH * VDIM, KVLAT, KVLAT, KVLAT, NHH * VDIM);

    // attention: S = scale * Q K^T (causal), softmax, O = P V
    float attn_scale = 1.0f / sqrtf((float)DQK);
    launch_gemm(true, s->q, s->kfull, s->S, TT, TT, DQK,
                NHH * DQK, NHH * DQK, TT,
                DQK, DQK, (long long)TT * TT, NHH,
                attn_scale, /*causal=*/1, 0, nullptr, nullptr, nullptr, nullptr, 0);
    softmax_causal_k<<<dim3(TT, NHH), 256>>>();
    launch_gemm(false, s->S, s->v, s->o, TT, VDIM, TT,
                TT, NHH * VDIM, NHH * VDIM,
                (long long)TT * TT, VDIM, VDIM, NHH,
                1.f, 0, /*klim=*/1, nullptr, nullptr, nullptr, nullptr, 0);

    // attn out + residual -> x2 (output part 1)
    launch_nt(s->o, wo, s->attn, TT, HH, NHH * VDIM, NHH * VDIM, NHH * VDIM, HH);
    x2_out_k<<<4096, 256>>>(s->x1, s->attn, s->x2, out, n);

    // n2 and MoE gating
    rmsnorm_k<<<TT, 256>>>(s->x2, ln2, s->n2, HH, HH, HH);
    gate_topk_k<<<TT, 256>>>(s->n2, gw);

    // shared FFN
    launch_nt(s->n2, wsup, s->hs, TT, 2 * SHI, HH, HH, HH, 2 * SHI);
    silu_gate_k<<<TT, 256>>>(s->hs, s->hsa, SHI);
    launch_nt(s->hsa, wsdn, s->shared_o, TT, HH, SHI, SHI, SHI, HH);

    // routed experts: batched over blockIdx.z = expert
    // up: h[e] = gather(n2, tok[e]) @ up[e]^T
    launch_gemm(true, s->n2, wup, s->h, TT, 2 * MIDIM, HH,
                HH, HH, 2 * MIDIM,
                0, (long long)(2 * MIDIM) * HH, (long long)TT * 2 * MIDIM, NE,
                1.f, 0, 0,
                s->tok, s->counts, nullptr, nullptr, TT);
    silu_gate_moe_k<<<dim3(TT, NE), 256>>>();
    // down: routed2[orow[e]] = ew[e] * (ha[e] @ dn[e]^T)
    launch_gemm(true, s->ha, wdn, s->routed2, TT, HH, MIDIM,
                MIDIM, MIDIM, HH,
                (long long)TT * MIDIM, (long long)HH * MIDIM, 0, NE,
                1.f, 0, 0,
                nullptr, s->counts, s->orow, s->ew, TT);

    // ffn = routed(slot0) + routed(slot1) + shared  (output part 2)
    combine_k<<<4096, 256>>>(s->routed2, s->shared_o, out + (long long)n, n);
}

// round 4
// speedup vs baseline: 4.9511x; 1.9598x over previous
#include <cuda_runtime.h>
#include <math.h>
#include <stdint.h>

#define TT   2048
#define HH   2048
#define NHH  16
#define NOPE 128
#define ROPED 64
#define DQK  192     // NOPE + ROPE
#define VDIM 128
#define QLAT 1536
#define KVLAT 512
#define NE   8
#define MIDIM 512
#define SHI  1024    // 2*MI

// ---------------------------------------------------------------------------
// Scratch (static device memory; no allocations anywhere)
// ---------------------------------------------------------------------------
struct __align__(128) Scratch {
    float x1[TT * HH];
    float n1[TT * HH];
    float qa_pre[TT * QLAT];
    float qa[TT * QLAT];
    float q[TT * NHH * DQK];
    float kv[TT * (KVLAT + ROPED)];
    float ckv[TT * KVLAT];
    float knope[TT * NHH * NOPE];
    float kfull[TT * NHH * DQK];
    float vT[NHH * VDIM * TT];          // [h*128+d, t]
    float S[(long long)NHH * TT * TT];  // 256 MB scores/probs
    float o[TT * NHH * VDIM];
    float attn[TT * HH];
    float x2[TT * HH];
    float n2[TT * HH];
    float h[(long long)NE * TT * 2 * MIDIM];
    float ha[(long long)NE * TT * MIDIM];
    float routed2[2 * TT * HH];
    float hs[TT * 2 * SHI];
    float hsa[TT * SHI];
    float shared_o[TT * HH];
    float ew[NE * TT];
    int   tok[NE * TT];
    int   orow[NE * TT];
    int   counts[NE];
    // tf32-rounded weight copies
    float wqa_r[QLAT * HH];
    float wqb_r[NHH * DQK * QLAT];
    float wkva_r[(KVLAT + ROPED) * HH];
    float wkb_r[NHH * NOPE * KVLAT];
    float wvb_r[NHH * VDIM * KVLAT];
    float wo_r[HH * NHH * VDIM];
    float wsup_r[2 * SHI * HH];
    float wsdn_r[HH * SHI];
    float wup_r[(long long)NE * 2 * MIDIM * HH];
    float wdn_r[(long long)NE * HH * MIDIM];
};
__device__ Scratch g_s;

// ---------------------------------------------------------------------------
// helpers
// ---------------------------------------------------------------------------
__device__ __forceinline__ float rna_tf32(float x) {
    unsigned y;
    asm("cvt.rna.tf32.f32 %0, %1;" : "=r"(y) : "f"(x));
    return __uint_as_float(y);
}

__device__ __forceinline__ uint32_t smem_u32(const void* p) {
    uint32_t a;
    asm("{ .reg .u64 t; cvta.to.shared.u64 t, %1; cvt.u32.u64 %0, t; }" : "=r"(a) : "l"(p));
    return a;
}

__device__ __forceinline__ void cp16(uint32_t dst, const void* src, int sz) {
    asm volatile("cp.async.cg.shared.global [%0], [%1], 16, %2;"
                 :: "r"(dst), "l"(src), "r"(sz));
}
__device__ __forceinline__ void cp_commit() {
    asm volatile("cp.async.commit_group;" ::: "memory");
}
__device__ __forceinline__ void cp_wait2() {
    asm volatile("cp.async.wait_group 2;" ::: "memory");
}

__device__ __forceinline__ void mma_tf32(float* d, const unsigned* a, const unsigned* b) {
    asm volatile(
        "mma.sync.aligned.m16n8k8.row.col.f32.tf32.tf32.f32 "
        "{%0,%1,%2,%3}, {%4,%5,%6,%7}, {%8,%9}, {%0,%1,%2,%3};\n"
        : "+f"(d[0]), "+f"(d[1]), "+f"(d[2]), "+f"(d[3])
        : "r"(a[0]), "r"(a[1]), "r"(a[2]), "r"(a[3]), "r"(b[0]), "r"(b[1]));
}

// ---------------------------------------------------------------------------
// NT tf32 GEMM via mma.sync: C[M,N] = scale * A[M,K] * B^T  (A:[M,K], B:[N,K])
// CTA 128x128, 4 warps (warp tile 64x64), ktile 32, 3-stage cp.async.
// smem layout per operand: row-major [row][32k], 16B-chunk XOR swizzle
//   chunk_phys = (k>>2) ^ (row&7)  -> conflict-free stores and fragment loads.
// ---------------------------------------------------------------------------
#define NSTAGE 3
#define STG_FLOATS 8192            // (128 A rows + 128 B rows) * 32 floats
#define SMEM_FLOATS (NSTAGE * STG_FLOATS)
#define SMEM_BYTES  (SMEM_FLOATS * 4)

__global__ __launch_bounds__(128)
void gemm_mm(const float* __restrict__ A, const float* __restrict__ B,
             float* __restrict__ C,
             int M, int N, int K, int lda, int ldb, int ldc,
             long long sA, long long sB, long long sC,
             float scale, int causal, int klim, int roundC,
             const int* __restrict__ aidx, const int* __restrict__ mdev,
             const int* __restrict__ cidx, const float* __restrict__ cscale,
             int pstride)
{
    extern __shared__ __align__(128) float smem[];
    const int z = blockIdx.z;
    A += (long long)z * sA;
    B += (long long)z * sB;
    C += (long long)z * sC;
    if (pstride) {
        if (mdev)   mdev   += z;
        if (aidx)   aidx   += (long long)z * pstride;
        if (cidx)   cidx   += (long long)z * pstride;
        if (cscale) cscale += (long long)z * pstride;
    }
    const int Meff = mdev ? *mdev : M;
    const int m0 = blockIdx.y * 128;
    const int n0 = blockIdx.x * 128;
    if (m0 >= Meff) return;
    if (causal && n0 > m0 + 127) return;
    const int kmax = klim ? min(K, m0 + 128) : K;
    const int ktiles = kmax >> 5;

    const uint32_t sbase = smem_u32(smem);
    const int tid = threadIdx.x;
    const int lane = tid & 31;
    const int wid = tid >> 5;
    const int wm = (wid & 1) * 64;
    const int wn = (wid >> 1) * 64;
    const int lr = lane >> 2;     // 0..7
    const int lm = lane & 3;      // 0..3

    float acc[4][8][4];
#pragma unroll
    for (int i = 0; i < 4; i++)
#pragma unroll
        for (int j = 0; j < 8; j++)
#pragma unroll
            for (int c = 0; c < 4; c++) acc[i][j][c] = 0.f;

    // float-index into smem: A row m chunk c -> s*8192 + m*32 + phys_c*4
    // B row n: + 4096
    auto issue_stage = [&](int i) {
        const int s = i % NSTAGE;
        const int kt = i << 5;
        const uint32_t abase = sbase + s * (STG_FLOATS * 4);
#pragma unroll
        for (int it = 0; it < 8; it++) {
            int c = tid + it * 128;          // 0..1023
            int row = c >> 3, ch = c & 7;
            int phys = ch ^ (row & 7);
            int gm = m0 + row;
            const float* src = A;
            int sz = 0;
            if (gm < Meff) {
                int ar = aidx ? aidx[gm] : gm;
                src = A + (long long)ar * lda + kt + ch * 4;
                sz = 16;
            }
            cp16(abase + (row * 32 + phys * 4) * 4, src, sz);
        }
#pragma unroll
        for (int it = 0; it < 8; it++) {
            int c = tid + it * 128;
            int row = c >> 3, ch = c & 7;
            int phys = ch ^ (row & 7);
            int gn = n0 + row;
            const float* src = B;
            int sz = 0;
            if (gn < N) {
                src = B + (long long)gn * ldb + kt + ch * 4;
                sz = 16;
            }
            cp16(abase + (4096 + row * 32 + phys * 4) * 4, src, sz);
        }
    };

    issue_stage(0); cp_commit();
    if (ktiles > 1) issue_stage(1);
    cp_commit();

    for (int i = 0; i < ktiles; i++) {
        __syncthreads();                       // all warps done with buf (i-1)
        if (i + 2 < ktiles) issue_stage(i + 2);
        cp_commit();
        cp_wait2();                            // stage i resident
        __syncthreads();

        const float* sa = smem + (i % NSTAGE) * STG_FLOATS;
        const float* sb = sa + 4096;
#pragma unroll
        for (int kk8 = 0; kk8 < 4; kk8++) {
            const int k0 = kk8 * 8 + lm;
            const int k1 = k0 + 4;
            const int c0 = (k0 >> 2) << 2;     // phys chunk base (pre-xor) *4 floats
            const int c1 = (k1 >> 2) << 2;
            unsigned afr[4][4], bfr[8][2];
#pragma unroll
            for (int im = 0; im < 4; im++) {
                int m = wm + im * 16 + lr;
                int mA = m & 7;
                afr[im][0] = __float_as_uint(sa[m * 32 + (c0 ^ (mA << 2)) + lm]);
                afr[im][2] = __float_as_uint(sa[m * 32 + (c1 ^ (mA << 2)) + lm]);
                int m8 = m + 8;
                afr[im][1] = __float_as_uint(sa[m8 * 32 + (c0 ^ (mA << 2)) + lm]);
                afr[im][3] = __float_as_uint(sa[m8 * 32 + (c1 ^ (mA << 2)) + lm]);
            }
#pragma unroll
            for (int jn = 0; jn < 8; jn++) {
                int nn = wn + jn * 8 + lr;
                int nA = (nn & 7) << 2;
                bfr[jn][0] = __float_as_uint(sb[nn * 32 + (c0 ^ nA) + lm]);
                bfr[jn][1] = __float_as_uint(sb[nn * 32 + (c1 ^ nA) + lm]);
            }
#pragma unroll
            for (int im = 0; im < 4; im++)
#pragma unroll
                for (int jn = 0; jn < 8; jn++)
                    mma_tf32(acc[im][jn], afr[im], bfr[jn]);
        }
    }

    // epilogue
#pragma unroll
    for (int im = 0; im < 4; im++) {
#pragma unroll
        for (int part = 0; part < 2; part++) {
            int gm = m0 + wm + im * 16 + lr + part * 8;
            if (gm >= Meff) continue;
            long long crow = gm;
            float w = scale;
            if (cidx) { crow = cidx[gm]; w = scale * cscale[gm]; }
            float* cp = C + crow * (long long)ldc;
#pragma unroll
            for (int jn = 0; jn < 8; jn++) {
                int gn = n0 + wn + jn * 8 + lm * 2;
                if (gn < N) {
                    float2 v2;
                    v2.x = acc[im][jn][part * 2] * w;
                    v2.y = acc[im][jn][part * 2 + 1] * w;
                    if (roundC) { v2.x = rna_tf32(v2.x); v2.y = rna_tf32(v2.y); }
                    *reinterpret_cast<float2*>(cp + gn) = v2;
                }
            }
        }
    }
}

// ---------------------------------------------------------------------------
// Elementwise / reduction kernels
// ---------------------------------------------------------------------------
__global__ void zero_counts_k() {
    if (threadIdx.x < NE) g_s.counts[threadIdx.x] = 0;
}

__global__ void round_copy_k(const float* __restrict__ in, float* __restrict__ out,
                             long long n) {
    for (long long i = blockIdx.x * (long long)blockDim.x + threadIdx.x; i < n;
         i += (long long)gridDim.x * blockDim.x)
        out[i] = rna_tf32(in[i]);
}

__global__ void add2_k(const float* __restrict__ a, const float* __restrict__ b,
                       float* __restrict__ c, int n) {
    for (int i = blockIdx.x * blockDim.x + threadIdx.x; i < n; i += gridDim.x * blockDim.x)
        c[i] = a[i] + b[i];
}

__global__ void x2_out_k(const float* __restrict__ x1, const float* __restrict__ attn,
                         float* __restrict__ x2, float* __restrict__ dout, int n) {
    for (int i = blockIdx.x * blockDim.x + threadIdx.x; i < n; i += gridDim.x * blockDim.x) {
        float v = x1[i] + attn[i];
        x2[i] = v;
        dout[i] = v;
    }
}

__global__ void combine_k(const float* __restrict__ routed2, const float* __restrict__ sh,
                          float* __restrict__ dout, int n) {
    for (int i = blockIdx.x * blockDim.x + threadIdx.x; i < n; i += gridDim.x * blockDim.x)
        dout[i] = routed2[i] + routed2[n + i] + sh[i];
}

__global__ __launch_bounds__(256)
void rmsnorm_k(const float* __restrict__ in, const float* __restrict__ w,
               float* __restrict__ out, int cols, int instride, int outstride) {
    int row = blockIdx.x;
    const float* ip = in + (long long)row * instride;
    float ss = 0.f;
    for (int j = threadIdx.x; j < cols; j += 256) { float v = ip[j]; ss += v * v; }
    __shared__ float red[256];
    red[threadIdx.x] = ss;
    __syncthreads();
    for (int st = 128; st > 0; st >>= 1) {
        if (threadIdx.x < st) red[threadIdx.x] += red[threadIdx.x + st];
        __syncthreads();
    }
    float scale = rsqrtf(red[0] / (float)cols + 1e-6f);
    float* op = out + (long long)row * outstride;
    for (int j = threadIdx.x; j < cols; j += 256)
        op[j] = rna_tf32(ip[j] * scale * w[j]);
}

__global__ void rope_q_k(float* __restrict__ q, const float* __restrict__ rsin,
                         const float* __restrict__ rcos) {
    int t = blockIdx.x;
    for (int i = threadIdx.x; i < NHH * 32; i += blockDim.x) {
        int h = i >> 5;
        int p = i & 31;
        float* base = q + (long long)t * (NHH * DQK) + h * DQK + NOPE + 2 * p;
        float s = rsin[t * 32 + p], c = rcos[t * 32 + p];
        float a = base[0], b = base[1];
        base[0] = rna_tf32(a * c - b * s);
        base[1] = rna_tf32(a * s + b * c);
    }
}

__global__ void build_k_k(const float* __restrict__ knope, const float* __restrict__ kv,
                          const float* __restrict__ rsin, const float* __restrict__ rcos,
                          float* __restrict__ kfull) {
    int t = blockIdx.x;
    __shared__ float pe[ROPED];
    if (threadIdx.x < 32) {
        int p = threadIdx.x;
        float a = kv[(long long)t * (KVLAT + ROPED) + KVLAT + 2 * p];
        float b = kv[(long long)t * (KVLAT + ROPED) + KVLAT + 2 * p + 1];
        float s = rsin[t * 32 + p], c = rcos[t * 32 + p];
        pe[2 * p]     = rna_tf32(a * c - b * s);
        pe[2 * p + 1] = rna_tf32(a * s + b * c);
    }
    __syncthreads();
    for (int i = threadIdx.x; i < NHH * DQK; i += blockDim.x) {
        int h = i / DQK;
        int d = i % DQK;
        kfull[(long long)t * (NHH * DQK) + i] =
            (d < NOPE) ? knope[(long long)t * (NHH * NOPE) + h * NOPE + d] : pe[d - NOPE];
    }
}

__global__ __launch_bounds__(256)
void softmax_causal_k() {
    int qrow = blockIdx.x;
    int h = blockIdx.y;
    float* row = g_s.S + ((long long)h * TT + qrow) * TT;
    int len = qrow + 1;
    __shared__ float red[256];

    float m = -1e30f;
    for (int k = threadIdx.x; k < len; k += 256) m = fmaxf(m, row[k]);
    red[threadIdx.x] = m;
    __syncthreads();
    for (int st = 128; st > 0; st >>= 1) {
        if (threadIdx.x < st) red[threadIdx.x] = fmaxf(red[threadIdx.x], red[threadIdx.x + st]);
        __syncthreads();
    }
    m = red[0];
    __syncthreads();

    float s = 0.f;
    for (int k = threadIdx.x; k < len; k += 256) {
        float e = __expf(row[k] - m);
        row[k] = e;
        s += e;
    }
    red[threadIdx.x] = s;
    __syncthreads();
    for (int st = 128; st > 0; st >>= 1) {
        if (threadIdx.x < st) red[threadIdx.x] += red[threadIdx.x + st];
        __syncthreads();
    }
    float inv = 1.0f / red[0];
    for (int k = threadIdx.x; k < len; k += 256) row[k] = rna_tf32(row[k] * inv);
    for (int k = len + threadIdx.x; k < TT; k += 256) row[k] = 0.f;
}

__global__ __launch_bounds__(256)
void gate_topk_k(const float* __restrict__ n2, const float* __restrict__ gw) {
    int t = blockIdx.x;
    __shared__ float logits[NE];
    int warp = threadIdx.x >> 5, lane = threadIdx.x & 31;
    const float* xp = n2 + (long long)t * HH;
    const float* wp = gw + warp * HH;
    float s = 0.f;
    for (int k = lane; k < HH; k += 32) s += xp[k] * wp[k];
    for (int off = 16; off > 0; off >>= 1) s += __shfl_down_sync(0xffffffffu, s, off);
    if (lane == 0) logits[warp] = s;
    __syncthreads();
    if (threadIdx.x == 0) {
        float m = logits[0];
        for (int e = 1; e < NE; e++) m = fmaxf(m, logits[e]);
        float p[NE];
        float sum = 0.f;
        for (int e = 0; e < NE; e++) { p[e] = __expf(logits[e] - m); sum += p[e]; }
        for (int e = 0; e < NE; e++) p[e] /= sum;
        int i0 = 0;
        for (int e = 1; e < NE; e++) if (p[e] > p[i0]) i0 = e;
        int i1 = -1;
        for (int e = 0; e < NE; e++) {
            if (e == i0) continue;
            if (i1 < 0 || p[e] > p[i1]) i1 = e;
        }
        float w0 = p[i0], w1 = p[i1];
        float tot = w0 + w1;
        w0 /= tot; w1 /= tot;
        int pos0 = atomicAdd(&g_s.counts[i0], 1);
        g_s.tok[i0 * TT + pos0] = t;
        g_s.orow[i0 * TT + pos0] = t;
        g_s.ew[i0 * TT + pos0] = w0;
        int pos1 = atomicAdd(&g_s.counts[i1], 1);
        g_s.tok[i1 * TT + pos1] = t;
        g_s.orow[i1 * TT + pos1] = TT + t;
        g_s.ew[i1 * TT + pos1] = w1;
    }
}

__global__ void silu_gate_k(const float* __restrict__ in, float* __restrict__ out,
                            int half) {
    int row = blockIdx.x;
    const float* ip = in + (long long)row * 2 * half;
    float* op = out + (long long)row * half;
    for (int j = threadIdx.x; j < half; j += blockDim.x) {
        float a = ip[j], b = ip[half + j];
        op[j] = rna_tf32((a / (1.f + __expf(-a))) * b);
    }
}

__global__ void silu_gate_moe_k() {
    int e = blockIdx.y;
    int row = blockIdx.x;
    if (row >= g_s.counts[e]) return;
    const float* ip = g_s.h + ((long long)e * TT + row) * (2 * MIDIM);
    float* op = g_s.ha + ((long long)e * TT + row) * MIDIM;
    for (int j = threadIdx.x; j < MIDIM; j += blockDim.x) {
        float a = ip[j], b = ip[MIDIM + j];
        op[j] = rna_tf32((a / (1.f + __expf(-a))) * b);
    }
}

// ---------------------------------------------------------------------------
// Host-side launch helpers
// ---------------------------------------------------------------------------
static void launch_gemm(const float* A, const float* B, float* C,
                        int M, int N, int K, int lda, int ldb, int ldc,
                        long long sA, long long sB, long long sC, int bz,
                        float sc, int causal, int klim, int roundC,
                        const int* aidx, const int* mdev,
                        const int* cidx, const float* cs, int pstride)
{
    dim3 grid((N + 127) / 128, (M + 127) / 128, bz);
    gemm_mm<<<grid, 128, SMEM_BYTES>>>(A, B, C, M, N, K, lda, ldb, ldc,
                                       sA, sB, sC, sc, causal, klim, roundC,
                                       aidx, mdev, cidx, cs, pstride);
}

static void launch_nt(const float* A, const float* B, float* C, int M, int N, int K,
                      int lda, int ldb, int ldc, int roundC)
{
    launch_gemm(A, B, C, M, N, K, lda, ldb, ldc, 0, 0, 0, 1, 1.f, 0, 0, roundC,
                nullptr, nullptr, nullptr, nullptr, 0);
}

// ---------------------------------------------------------------------------
extern "C" void kernel_launch(void* const* d_in, const int* in_sizes, int n_in,
                              void* d_out, int out_size)
{
    const float* x    = (const float*)d_in[0];
    const float* skip = (const float*)d_in[1];
    const float* rsin = (const float*)d_in[2];
    const float* rcos = (const float*)d_in[3];
    const float* ln1  = (const float*)d_in[4];
    const float* ln2  = (const float*)d_in[5];
    const float* wqa  = (const float*)d_in[6];
    const float* qan  = (const float*)d_in[7];
    const float* wqb  = (const float*)d_in[8];
    const float* wkva = (const float*)d_in[9];
    const float* kvan = (const float*)d_in[10];
    const float* wkb  = (const float*)d_in[11];
    const float* wvb  = (const float*)d_in[12];
    const float* wo   = (const float*)d_in[13];
    const float* gw   = (const float*)d_in[14];
    const float* wup  = (const float*)d_in[15];
    const float* wdn  = (const float*)d_in[16];
    const float* wsup = (const float*)d_in[17];
    const float* wsdn = (const float*)d_in[18];
    float* out = (float*)d_out;

    Scratch* s = nullptr;
    cudaGetSymbolAddress((void**)&s, g_s);
    cudaFuncSetAttribute(gemm_mm, cudaFuncAttributeMaxDynamicSharedMemorySize,
                         SMEM_BYTES);

    const int n = TT * HH;

    zero_counts_k<<<1, 32>>>();

    // round weights into tf32 grid
    round_copy_k<<<2048, 256>>>(wqa,  s->wqa_r,  (long long)QLAT * HH);
    round_copy_k<<<2048, 256>>>(wqb,  s->wqb_r,  (long long)NHH * DQK * QLAT);
    round_copy_k<<<2048, 256>>>(wkva, s->wkva_r, (long long)(KVLAT + ROPED) * HH);
    round_copy_k<<<2048, 256>>>(wkb,  s->wkb_r,  (long long)NHH * NOPE * KVLAT);
    round_copy_k<<<2048, 256>>>(wvb,  s->wvb_r,  (long long)NHH * VDIM * KVLAT);
    round_copy_k<<<2048, 256>>>(wo,   s->wo_r,   (long long)HH * NHH * VDIM);
    round_copy_k<<<2048, 256>>>(wsup, s->wsup_r, (long long)2 * SHI * HH);
    round_copy_k<<<2048, 256>>>(wsdn, s->wsdn_r, (long long)HH * SHI);
    round_copy_k<<<4096, 256>>>(wup,  s->wup_r,  (long long)NE * 2 * MIDIM * HH);
    round_copy_k<<<4096, 256>>>(wdn,  s->wdn_r,  (long long)NE * HH * MIDIM);

    // x1 = x + skip ; n1 = rms(x1)
    add2_k<<<4096, 256>>>(x, skip, s->x1, n);
    rmsnorm_k<<<TT, 256>>>(s->x1, ln1, s->n1, HH, HH, HH);

    // q path
    launch_nt(s->n1, s->wqa_r, s->qa_pre, TT, QLAT, HH, HH, HH, QLAT, 0);
    rmsnorm_k<<<TT, 256>>>(s->qa_pre, qan, s->qa, QLAT, QLAT, QLAT);
    launch_nt(s->qa, s->wqb_r, s->q, TT, NHH * DQK, QLAT, QLAT, QLAT, NHH * DQK, 1);
    rope_q_k<<<TT, 256>>>(s->q, rsin, rcos);

    // kv path
    launch_nt(s->n1, s->wkva_r, s->kv, TT, KVLAT + ROPED, HH, HH, HH, KVLAT + ROPED, 0);
    rmsnorm_k<<<TT, 256>>>(s->kv, kvan, s->ckv, KVLAT, KVLAT + ROPED, KVLAT);
    launch_nt(s->ckv, s->wkb_r, s->knope, TT, NHH * NOPE, KVLAT, KVLAT, KVLAT, NHH * NOPE, 1);
    build_k_k<<<TT, 256>>>(s->knope, s->kv, rsin, rcos, s->kfull);
    // vT[h*128+d, t] = sum_k wvb[h*128+d, k] * ckv[t, k]
    launch_nt(s->wvb_r, s->ckv, s->vT, NHH * VDIM, TT, KVLAT, KVLAT, KVLAT, TT, 1);

    // attention
    float attn_scale = 1.0f / sqrtf((float)DQK);
    launch_gemm(s->q, s->kfull, s->S, TT, TT, DQK,
                NHH * DQK, NHH * DQK, TT,
                DQK, DQK, (long long)TT * TT, NHH,
                attn_scale, /*causal=*/1, 0, 0, nullptr, nullptr, nullptr, nullptr, 0);
    softmax_causal_k<<<dim3(TT, NHH), 256>>>();
    // O[q, h*128+d] = sum_k P[h][q,k] * vT[h*128+d, k]   (NT form via vT)
    launch_gemm(s->S, s->vT, s->o, TT, VDIM, TT,
                TT, TT, NHH * VDIM,
                (long long)TT * TT, (long long)VDIM * TT, VDIM, NHH,
                1.f, 0, /*klim=*/1, 1, nullptr, nullptr, nullptr, nullptr, 0);

    // attn out + residual -> x2 (output part 1)
    launch_nt(s->o, s->wo_r, s->attn, TT, HH, NHH * VDIM, NHH * VDIM, NHH * VDIM, HH, 0);
    x2_out_k<<<4096, 256>>>(s->x1, s->attn, s->x2, out, n);

    // n2 and MoE gating
    rmsnorm_k<<<TT, 256>>>(s->x2, ln2, s->n2, HH, HH, HH);
    gate_topk_k<<<TT, 256>>>(s->n2, gw);

    // shared FFN
    launch_nt(s->n2, s->wsup_r, s->hs, TT, 2 * SHI, HH, HH, HH, 2 * SHI, 0);
    silu_gate_k<<<TT, 256>>>(s->hs, s->hsa, SHI);
    launch_nt(s->hsa, s->wsdn_r, s->shared_o, TT, HH, SHI, SHI, SHI, HH, 0);

    // routed experts: batched over blockIdx.z = expert
    launch_gemm(s->n2, s->wup_r, s->h, TT, 2 * MIDIM, HH,
                HH, HH, 2 * MIDIM,
                0, (long long)(2 * MIDIM) * HH, (long long)TT * 2 * MIDIM, NE,
                1.f, 0, 0, 0,
                s->tok, s->counts, nullptr, nullptr, TT);
    silu_gate_moe_k<<<dim3(TT, NE), 256>>>();
    launch_gemm(s->ha, s->wdn_r, s->routed2, TT, HH, MIDIM,
                MIDIM, MIDIM, HH,
                (long long)TT * MIDIM, (long long)HH * MIDIM, 0, NE,
                1.f, 0, 0, 0,
                nullptr, s->counts, s->orow, s->ew, TT);

    // ffn = routed(slot0) + routed(slot1) + shared  (output part 2)
    combine_k<<<4096, 256>>>(s->routed2, s->shared_o, out + (long long)n, n);
}

// round 5
// speedup vs baseline: 7.8652x; 1.5886x over previous
#include <cuda_runtime.h>
#include <cuda_fp16.h>
#include <math.h>
#include <stdint.h>

#define TT   2048
#define HH   2048
#define NHH  16
#define NOPE 128
#define ROPED 64
#define DQK  192     // NOPE + ROPE
#define VDIM 128
#define QLAT 1536
#define KVLAT 512
#define NE   8
#define MIDIM 512
#define SHI  1024    // 2*MI

// ---------------------------------------------------------------------------
// Scratch (static device memory; no allocations anywhere)
// ---------------------------------------------------------------------------
struct __align__(128) Scratch {
    // f32 buffers
    float x1[TT * HH];
    float qa_pre[TT * QLAT];
    float kv[TT * (KVLAT + ROPED)];
    float S[(long long)NHH * TT * TT];   // 256 MB scores
    float attn[TT * HH];
    float x2[TT * HH];
    float h[(long long)NE * TT * 2 * MIDIM];
    float hs[TT * 2 * SHI];
    float routed2[2 * TT * HH];
    float shared_o[TT * HH];
    float ew[NE * TT];
    int   tok[NE * TT];
    int   orow[NE * TT];
    int   counts[NE];
    // half activation buffers
    __half n1h[TT * HH];
    __half qah[TT * QLAT];
    __half qh[TT * NHH * DQK];
    __half ckvh[TT * KVLAT];
    __half knopeh[TT * NHH * NOPE];
    __half kfullh[TT * NHH * DQK];
    __half vTh[NHH * VDIM * TT];          // [h*128+d, t]
    __half Sh[(long long)NHH * TT * TT];  // 128 MB probs
    __half oh[TT * NHH * VDIM];
    __half n2h[TT * HH];
    __half hsah[TT * SHI];
    __half hah[(long long)NE * TT * MIDIM];
    // half weight copies
    __half wqa_h[QLAT * HH];
    __half wqb_h[NHH * DQK * QLAT];
    __half wkva_h[(KVLAT + ROPED) * HH];
    __half wkb_h[NHH * NOPE * KVLAT];
    __half wvb_h[NHH * VDIM * KVLAT];
    __half wo_h[HH * NHH * VDIM];
    __half wsup_h[2 * SHI * HH];
    __half wsdn_h[HH * SHI];
    __half wup_h[(long long)NE * 2 * MIDIM * HH];
    __half wdn_h[(long long)NE * HH * MIDIM];
};
__device__ Scratch g_s;

// ---------------------------------------------------------------------------
// helpers
// ---------------------------------------------------------------------------
__device__ __forceinline__ uint32_t smem_u32(const void* p) {
    uint32_t a;
    asm("{ .reg .u64 t; cvta.to.shared.u64 t, %1; cvt.u32.u64 %0, t; }" : "=r"(a) : "l"(p));
    return a;
}

__device__ __forceinline__ void cp16(uint32_t dst, const void* src, int sz) {
    asm volatile("cp.async.cg.shared.global [%0], [%1], 16, %2;"
                 :: "r"(dst), "l"(src), "r"(sz));
}
__device__ __forceinline__ void cp_commit() {
    asm volatile("cp.async.commit_group;" ::: "memory");
}
__device__ __forceinline__ void cp_wait2() {
    asm volatile("cp.async.wait_group 2;" ::: "memory");
}

__device__ __forceinline__ void ldm_x4(unsigned& r0, unsigned& r1, unsigned& r2,
                                       unsigned& r3, uint32_t addr) {
    asm volatile("ldmatrix.sync.aligned.m8n8.x4.shared.b16 {%0,%1,%2,%3}, [%4];"
                 : "=r"(r0), "=r"(r1), "=r"(r2), "=r"(r3) : "r"(addr));
}

__device__ __forceinline__ void mma_f16(float* d, const unsigned* a, const unsigned* b) {
    asm volatile(
        "mma.sync.aligned.m16n8k16.row.col.f32.f16.f16.f32 "
        "{%0,%1,%2,%3}, {%4,%5,%6,%7}, {%8,%9}, {%0,%1,%2,%3};\n"
        : "+f"(d[0]), "+f"(d[1]), "+f"(d[2]), "+f"(d[3])
        : "r"(a[0]), "r"(a[1]), "r"(a[2]), "r"(a[3]), "r"(b[0]), "r"(b[1]));
}

// ---------------------------------------------------------------------------
// fp16 NT GEMM via mma.sync: C[M,N] = scale * A[M,K] * B^T  (A:[M,K], B:[N,K] half)
// CTA 128x128, 4 warps (warp tile 64x64), ktile 64 halves (128B rows).
// smem: 256 rows (128 A + 128 B) x 128B, 16B-chunk swizzle ch^(row&7).
// 3-stage cp.async. Fragments via ldmatrix.x4. OUTH: write half C.
// ---------------------------------------------------------------------------
#define NSTAGE 3
#define STG_BYTES 32768
#define SMEM_BYTES (NSTAGE * STG_BYTES)

template <bool OUTH>
__global__ __launch_bounds__(128)
void gemm_h(const __half* __restrict__ A, const __half* __restrict__ B,
            void* __restrict__ Cv,
            int M, int N, int K, int lda, int ldb, int ldc,
            long long sA, long long sB, long long sC,
            float scale, int causal, int klim,
            const int* __restrict__ aidx, const int* __restrict__ mdev,
            const int* __restrict__ cidx, const float* __restrict__ cscale,
            int pstride)
{
    extern __shared__ __align__(128) char smem[];
    const int z = blockIdx.z;
    A += (long long)z * sA;
    B += (long long)z * sB;
    if (pstride) {
        if (mdev)   mdev   += z;
        if (aidx)   aidx   += (long long)z * pstride;
        if (cidx)   cidx   += (long long)z * pstride;
        if (cscale) cscale += (long long)z * pstride;
    }
    const int Meff = mdev ? *mdev : M;
    const int m0 = blockIdx.y * 128;
    const int n0 = blockIdx.x * 128;
    if (m0 >= Meff) return;
    if (causal && n0 > m0 + 127) return;
    const int kmax = klim ? min(K, m0 + 128) : K;
    const int ktiles = kmax >> 6;

    const uint32_t sbase = smem_u32(smem);
    const int tid = threadIdx.x;
    const int lane = tid & 31;
    const int wid = tid >> 5;
    const int wm = (wid & 1) * 64;
    const int wn = (wid >> 1) * 64;
    const int lr = lane >> 2;     // 0..7
    const int lm = lane & 3;      // 0..3

    float acc[4][8][4];
#pragma unroll
    for (int i = 0; i < 4; i++)
#pragma unroll
        for (int j = 0; j < 8; j++)
#pragma unroll
            for (int c = 0; c < 4; c++) acc[i][j][c] = 0.f;

    auto issue_stage = [&](int i) {
        const uint32_t base = sbase + (i % NSTAGE) * STG_BYTES;
        const int kt = i << 6;           // half offset
#pragma unroll
        for (int it = 0; it < 16; it++) {
            int c = tid + it * 128;      // 0..2047
            int row = c >> 3, ch = c & 7;
            uint32_t dst = base + row * 128 + ((ch ^ (row & 7)) << 4);
            const __half* src;
            int sz = 0;
            if (row < 128) {
                int gm = m0 + row;
                src = A;
                if (gm < Meff) {
                    int ar = aidx ? aidx[gm] : gm;
                    src = A + (long long)ar * lda + kt + ch * 8;
                    sz = 16;
                }
            } else {
                int gn = n0 + row - 128;
                src = B;
                if (gn < N) {
                    src = B + (long long)gn * ldb + kt + ch * 8;
                    sz = 16;
                }
            }
            cp16(dst, src, sz);
        }
    };

    issue_stage(0); cp_commit();
    if (ktiles > 1) issue_stage(1);
    cp_commit();

    // ldmatrix lane address components
    const int a_row = lane & 15;          // row within 16 (tiles 0,1 / 2,3)
    const int a_h = lane >> 4;            // k-chunk half select
    const int b_t = lane >> 3;            // tile index 0..3
    const int b_r = lane & 7;

    for (int i = 0; i < ktiles; i++) {
        __syncthreads();
        if (i + 2 < ktiles) issue_stage(i + 2);
        cp_commit();
        cp_wait2();
        __syncthreads();

        const uint32_t base = sbase + (i % NSTAGE) * STG_BYTES;
#pragma unroll
        for (int kk = 0; kk < 4; kk++) {
            unsigned afr[4][4], bfr[8][2];
#pragma unroll
            for (int im = 0; im < 4; im++) {
                int row = wm + im * 16 + a_row;
                int ch = kk * 2 + a_h;
                ldm_x4(afr[im][0], afr[im][1], afr[im][2], afr[im][3],
                       base + row * 128 + ((ch ^ (row & 7)) << 4));
            }
#pragma unroll
            for (int j2 = 0; j2 < 4; j2++) {
                int jn = j2 * 2 + (b_t >> 1);
                int row = 128 + wn + jn * 8 + b_r;
                int ch = kk * 2 + (b_t & 1);
                unsigned r0, r1, r2, r3;
                ldm_x4(r0, r1, r2, r3, base + row * 128 + ((ch ^ (row & 7)) << 4));
                bfr[j2 * 2][0] = r0;     bfr[j2 * 2][1] = r1;
                bfr[j2 * 2 + 1][0] = r2; bfr[j2 * 2 + 1][1] = r3;
            }
#pragma unroll
            for (int im = 0; im < 4; im++)
#pragma unroll
                for (int jn = 0; jn < 8; jn++)
                    mma_f16(acc[im][jn], afr[im], bfr[jn]);
        }
    }

    // epilogue
#pragma unroll
    for (int im = 0; im < 4; im++) {
#pragma unroll
        for (int part = 0; part < 2; part++) {
            int gm = m0 + wm + im * 16 + lr + part * 8;
            if (gm >= Meff) continue;
            long long crow = gm;
            float w = scale;
            if (cidx) { crow = cidx[gm]; w = scale * cscale[gm]; }
#pragma unroll
            for (int jn = 0; jn < 8; jn++) {
                int gn = n0 + wn + jn * 8 + lm * 2;
                if (gn >= N) continue;
                float vx = acc[im][jn][part * 2] * w;
                float vy = acc[im][jn][part * 2 + 1] * w;
                if (OUTH) {
                    __half* cp = (__half*)Cv + ((long long)z * sC) + crow * (long long)ldc + gn;
                    *reinterpret_cast<__half2*>(cp) = __floats2half2_rn(vx, vy);
                } else {
                    float* cp = (float*)Cv + ((long long)z * sC) + crow * (long long)ldc + gn;
                    *reinterpret_cast<float2*>(cp) = make_float2(vx, vy);
                }
            }
        }
    }
}

// ---------------------------------------------------------------------------
// Elementwise / reduction kernels
// ---------------------------------------------------------------------------
__global__ void zero_counts_k() {
    if (threadIdx.x < NE) g_s.counts[threadIdx.x] = 0;
}

__global__ void f2h_k(const float* __restrict__ in, __half* __restrict__ out,
                      long long n) {
    for (long long i = blockIdx.x * (long long)blockDim.x + threadIdx.x; i < n;
         i += (long long)gridDim.x * blockDim.x)
        out[i] = __float2half_rn(in[i]);
}

__global__ void add2_k(const float* __restrict__ a, const float* __restrict__ b,
                       float* __restrict__ c, int n) {
    for (int i = blockIdx.x * blockDim.x + threadIdx.x; i < n; i += gridDim.x * blockDim.x)
        c[i] = a[i] + b[i];
}

__global__ void x2_out_k(const float* __restrict__ x1, const float* __restrict__ attn,
                         float* __restrict__ x2, float* __restrict__ dout, int n) {
    for (int i = blockIdx.x * blockDim.x + threadIdx.x; i < n; i += gridDim.x * blockDim.x) {
        float v = x1[i] + attn[i];
        x2[i] = v;
        dout[i] = v;
    }
}

__global__ void combine_k(const float* __restrict__ routed2, const float* __restrict__ sh,
                          float* __restrict__ dout, int n) {
    for (int i = blockIdx.x * blockDim.x + threadIdx.x; i < n; i += gridDim.x * blockDim.x)
        dout[i] = routed2[i] + routed2[n + i] + sh[i];
}

// f32 in -> half out
__global__ __launch_bounds__(256)
void rmsnorm_h_k(const float* __restrict__ in, const float* __restrict__ w,
                 __half* __restrict__ out, int cols, int instride, int outstride) {
    int row = blockIdx.x;
    const float* ip = in + (long long)row * instride;
    float ss = 0.f;
    for (int j = threadIdx.x; j < cols; j += 256) { float v = ip[j]; ss += v * v; }
    __shared__ float red[256];
    red[threadIdx.x] = ss;
    __syncthreads();
    for (int st = 128; st > 0; st >>= 1) {
        if (threadIdx.x < st) red[threadIdx.x] += red[threadIdx.x + st];
        __syncthreads();
    }
    float scale = rsqrtf(red[0] / (float)cols + 1e-6f);
    __half* op = out + (long long)row * outstride;
    for (int j = threadIdx.x; j < cols; j += 256)
        op[j] = __float2half_rn(ip[j] * scale * w[j]);
}

__global__ void rope_q_k(__half* __restrict__ q, const float* __restrict__ rsin,
                         const float* __restrict__ rcos) {
    int t = blockIdx.x;
    for (int i = threadIdx.x; i < NHH * 32; i += blockDim.x) {
        int h = i >> 5;
        int p = i & 31;
        __half* base = q + (long long)t * (NHH * DQK) + h * DQK + NOPE + 2 * p;
        float s = rsin[t * 32 + p], c = rcos[t * 32 + p];
        float a = __half2float(base[0]), b = __half2float(base[1]);
        base[0] = __float2half_rn(a * c - b * s);
        base[1] = __float2half_rn(a * s + b * c);
    }
}

__global__ void build_k_k(const __half* __restrict__ knope, const float* __restrict__ kv,
                          const float* __restrict__ rsin, const float* __restrict__ rcos,
                          __half* __restrict__ kfull) {
    int t = blockIdx.x;
    __shared__ __half pe[ROPED];
    if (threadIdx.x < 32) {
        int p = threadIdx.x;
        float a = kv[(long long)t * (KVLAT + ROPED) + KVLAT + 2 * p];
        float b = kv[(long long)t * (KVLAT + ROPED) + KVLAT + 2 * p + 1];
        float s = rsin[t * 32 + p], c = rcos[t * 32 + p];
        pe[2 * p]     = __float2half_rn(a * c - b * s);
        pe[2 * p + 1] = __float2half_rn(a * s + b * c);
    }
    __syncthreads();
    for (int i = threadIdx.x; i < NHH * DQK; i += blockDim.x) {
        int h = i / DQK;
        int d = i % DQK;
        kfull[(long long)t * (NHH * DQK) + i] =
            (d < NOPE) ? knope[(long long)t * (NHH * NOPE) + h * NOPE + d] : pe[d - NOPE];
    }
}

// softmax: f32 scores -> half probs, zero fill to tile end
__global__ __launch_bounds__(256)
void softmax_causal_k() {
    int qrow = blockIdx.x;
    int h = blockIdx.y;
    const float* row = g_s.S + ((long long)h * TT + qrow) * TT;
    __half* orow = g_s.Sh + ((long long)h * TT + qrow) * TT;
    int len = qrow + 1;
    int fill_end = (qrow & ~127) + 128;
    __shared__ float redm[256], reds[256];

    // online max + sum in one pass
    float m = -1e30f, sum = 0.f;
    for (int k = threadIdx.x; k < len; k += 256) {
        float v = row[k];
        if (v > m) { sum *= __expf(m - v); m = v; }
        sum += __expf(v - m);
    }
    redm[threadIdx.x] = m;
    reds[threadIdx.x] = sum;
    __syncthreads();
    for (int st = 128; st > 0; st >>= 1) {
        if (threadIdx.x < st) {
            float m2 = redm[threadIdx.x + st], s2 = reds[threadIdx.x + st];
            float m1 = redm[threadIdx.x], s1 = reds[threadIdx.x];
            float mm = fmaxf(m1, m2);
            redm[threadIdx.x] = mm;
            reds[threadIdx.x] = s1 * __expf(m1 - mm) + s2 * __expf(m2 - mm);
        }
        __syncthreads();
    }
    m = redm[0];
    float inv = 1.0f / reds[0];

    for (int k = threadIdx.x; k < len; k += 256)
        orow[k] = __float2half_rn(__expf(row[k] - m) * inv);
    for (int k = len + threadIdx.x; k < fill_end; k += 256)
        orow[k] = __float2half_rn(0.f);
}

__global__ __launch_bounds__(256)
void gate_topk_k(const __half* __restrict__ n2, const float* __restrict__ gw) {
    int t = blockIdx.x;
    __shared__ float logits[NE];
    int warp = threadIdx.x >> 5, lane = threadIdx.x & 31;
    const __half* xp = n2 + (long long)t * HH;
    const float* wp = gw + warp * HH;
    float s = 0.f;
    for (int k = lane; k < HH; k += 32) s += __half2float(xp[k]) * wp[k];
    for (int off = 16; off > 0; off >>= 1) s += __shfl_down_sync(0xffffffffu, s, off);
    if (lane == 0) logits[warp] = s;
    __syncthreads();
    if (threadIdx.x == 0) {
        float m = logits[0];
        for (int e = 1; e < NE; e++) m = fmaxf(m, logits[e]);
        float p[NE];
        float sum = 0.f;
        for (int e = 0; e < NE; e++) { p[e] = __expf(logits[e] - m); sum += p[e]; }
        for (int e = 0; e < NE; e++) p[e] /= sum;
        int i0 = 0;
        for (int e = 1; e < NE; e++) if (p[e] > p[i0]) i0 = e;
        int i1 = -1;
        for (int e = 0; e < NE; e++) {
            if (e == i0) continue;
            if (i1 < 0 || p[e] > p[i1]) i1 = e;
        }
        float w0 = p[i0], w1 = p[i1];
        float tot = w0 + w1;
        w0 /= tot; w1 /= tot;
        int pos0 = atomicAdd(&g_s.counts[i0], 1);
        g_s.tok[i0 * TT + pos0] = t;
        g_s.orow[i0 * TT + pos0] = t;
        g_s.ew[i0 * TT + pos0] = w0;
        int pos1 = atomicAdd(&g_s.counts[i1], 1);
        g_s.tok[i1 * TT + pos1] = t;
        g_s.orow[i1 * TT + pos1] = TT + t;
        g_s.ew[i1 * TT + pos1] = w1;
    }
}

__global__ void silu_gate_k(const float* __restrict__ in, __half* __restrict__ out,
                            int half_) {
    int row = blockIdx.x;
    const float* ip = in + (long long)row * 2 * half_;
    __half* op = out + (long long)row * half_;
    for (int j = threadIdx.x; j < half_; j += blockDim.x) {
        float a = ip[j], b = ip[half_ + j];
        op[j] = __float2half_rn((a / (1.f + __expf(-a))) * b);
    }
}

__global__ void silu_gate_moe_k() {
    int e = blockIdx.y;
    int row = blockIdx.x;
    if (row >= g_s.counts[e]) return;
    const float* ip = g_s.h + ((long long)e * TT + row) * (2 * MIDIM);
    __half* op = g_s.hah + ((long long)e * TT + row) * MIDIM;
    for (int j = threadIdx.x; j < MIDIM; j += blockDim.x) {
        float a = ip[j], b = ip[MIDIM + j];
        op[j] = __float2half_rn((a / (1.f + __expf(-a))) * b);
    }
}

// ---------------------------------------------------------------------------
// Host-side launch helpers
// ---------------------------------------------------------------------------
static void launch_gemm(bool outh, const __half* A, const __half* B, void* C,
                        int M, int N, int K, int lda, int ldb, int ldc,
                        long long sA, long long sB, long long sC, int bz,
                        float sc, int causal, int klim,
                        const int* aidx, const int* mdev,
                        const int* cidx, const float* cs, int pstride)
{
    dim3 grid((N + 127) / 128, (M + 127) / 128, bz);
    if (outh)
        gemm_h<true><<<grid, 128, SMEM_BYTES>>>(A, B, C, M, N, K, lda, ldb, ldc,
                                                sA, sB, sC, sc, causal, klim,
                                                aidx, mdev, cidx, cs, pstride);
    else
        gemm_h<false><<<grid, 128, SMEM_BYTES>>>(A, B, C, M, N, K, lda, ldb, ldc,
                                                 sA, sB, sC, sc, causal, klim,
                                                 aidx, mdev, cidx, cs, pstride);
}

static void launch_nt(bool outh, const __half* A, const __half* B, void* C,
                      int M, int N, int K, int lda, int ldb, int ldc)
{
    launch_gemm(outh, A, B, C, M, N, K, lda, ldb, ldc, 0, 0, 0, 1, 1.f, 0, 0,
                nullptr, nullptr, nullptr, nullptr, 0);
}

// ---------------------------------------------------------------------------
extern "C" void kernel_launch(void* const* d_in, const int* in_sizes, int n_in,
                              void* d_out, int out_size)
{
    const float* x    = (const float*)d_in[0];
    const float* skip = (const float*)d_in[1];
    const float* rsin = (const float*)d_in[2];
    const float* rcos = (const float*)d_in[3];
    const float* ln1  = (const float*)d_in[4];
    const float* ln2  = (const float*)d_in[5];
    const float* wqa  = (const float*)d_in[6];
    const float* qan  = (const float*)d_in[7];
    const float* wqb  = (const float*)d_in[8];
    const float* wkva = (const float*)d_in[9];
    const float* kvan = (const float*)d_in[10];
    const float* wkb  = (const float*)d_in[11];
    const float* wvb  = (const float*)d_in[12];
    const float* wo   = (const float*)d_in[13];
    const float* gw   = (const float*)d_in[14];
    const float* wup  = (const float*)d_in[15];
    const float* wdn  = (const float*)d_in[16];
    const float* wsup = (const float*)d_in[17];
    const float* wsdn = (const float*)d_in[18];
    float* out = (float*)d_out;

    Scratch* s = nullptr;
    cudaGetSymbolAddress((void**)&s, g_s);
    cudaFuncSetAttribute(gemm_h<true>, cudaFuncAttributeMaxDynamicSharedMemorySize,
                         SMEM_BYTES);
    cudaFuncSetAttribute(gemm_h<false>, cudaFuncAttributeMaxDynamicSharedMemorySize,
                         SMEM_BYTES);

    const int n = TT * HH;

    zero_counts_k<<<1, 32>>>();

    // weights -> half
    f2h_k<<<2048, 256>>>(wqa,  s->wqa_h,  (long long)QLAT * HH);
    f2h_k<<<2048, 256>>>(wqb,  s->wqb_h,  (long long)NHH * DQK * QLAT);
    f2h_k<<<2048, 256>>>(wkva, s->wkva_h, (long long)(KVLAT + ROPED) * HH);
    f2h_k<<<2048, 256>>>(wkb,  s->wkb_h,  (long long)NHH * NOPE * KVLAT);
    f2h_k<<<2048, 256>>>(wvb,  s->wvb_h,  (long long)NHH * VDIM * KVLAT);
    f2h_k<<<2048, 256>>>(wo,   s->wo_h,   (long long)HH * NHH * VDIM);
    f2h_k<<<2048, 256>>>(wsup, s->wsup_h, (long long)2 * SHI * HH);
    f2h_k<<<2048, 256>>>(wsdn, s->wsdn_h, (long long)HH * SHI);
    f2h_k<<<4096, 256>>>(wup,  s->wup_h,  (long long)NE * 2 * MIDIM * HH);
    f2h_k<<<4096, 256>>>(wdn,  s->wdn_h,  (long long)NE * HH * MIDIM);

    // x1 = x + skip ; n1h = rms(x1)
    add2_k<<<4096, 256>>>(x, skip, s->x1, n);
    rmsnorm_h_k<<<TT, 256>>>(s->x1, ln1, s->n1h, HH, HH, HH);

    // q path
    launch_nt(false, s->n1h, s->wqa_h, s->qa_pre, TT, QLAT, HH, HH, HH, QLAT);
    rmsnorm_h_k<<<TT, 256>>>(s->qa_pre, qan, s->qah, QLAT, QLAT, QLAT);
    launch_nt(true, s->qah, s->wqb_h, s->qh, TT, NHH * DQK, QLAT, QLAT, QLAT, NHH * DQK);
    rope_q_k<<<TT, 256>>>(s->qh, rsin, rcos);

    // kv path
    launch_nt(false, s->n1h, s->wkva_h, s->kv, TT, KVLAT + ROPED, HH, HH, HH, KVLAT + ROPED);
    rmsnorm_h_k<<<TT, 256>>>(s->kv, kvan, s->ckvh, KVLAT, KVLAT + ROPED, KVLAT);
    launch_nt(true, s->ckvh, s->wkb_h, s->knopeh, TT, NHH * NOPE, KVLAT, KVLAT, KVLAT, NHH * NOPE);
    build_k_k<<<TT, 256>>>(s->knopeh, s->kv, rsin, rcos, s->kfullh);
    // vT[h*128+d, t] = sum_k wvb[h*128+d, k] * ckv[t, k]
    launch_nt(true, s->wvb_h, s->ckvh, s->vTh, NHH * VDIM, TT, KVLAT, KVLAT, KVLAT, TT);

    // attention
    float attn_scale = 1.0f / sqrtf((float)DQK);
    launch_gemm(false, s->qh, s->kfullh, s->S, TT, TT, DQK,
                NHH * DQK, NHH * DQK, TT,
                DQK, DQK, (long long)TT * TT, NHH,
                attn_scale, /*causal=*/1, 0, nullptr, nullptr, nullptr, nullptr, 0);
    softmax_causal_k<<<dim3(TT, NHH), 256>>>();
    // O[q, h*128+d] = sum_k P[h][q,k] * vT[h*128+d, k]
    launch_gemm(true, s->Sh, s->vTh, s->oh, TT, VDIM, TT,
                TT, TT, NHH * VDIM,
                (long long)TT * TT, (long long)VDIM * TT, VDIM, NHH,
                1.f, 0, /*klim=*/1, nullptr, nullptr, nullptr, nullptr, 0);

    // attn out + residual -> x2 (output part 1)
    launch_nt(false, s->oh, s->wo_h, s->attn, TT, HH, NHH * VDIM, NHH * VDIM, NHH * VDIM, HH);
    x2_out_k<<<4096, 256>>>(s->x1, s->attn, s->x2, out, n);

    // n2 and MoE gating
    rmsnorm_h_k<<<TT, 256>>>(s->x2, ln2, s->n2h, HH, HH, HH);
    gate_topk_k<<<TT, 256>>>(s->n2h, gw);

    // shared FFN
    launch_nt(false, s->n2h, s->wsup_h, s->hs, TT, 2 * SHI, HH, HH, HH, 2 * SHI);
    silu_gate_k<<<TT, 256>>>(s->hs, s->hsah, SHI);
    launch_nt(false, s->hsah, s->wsdn_h, s->shared_o, TT, HH, SHI, SHI, SHI, HH);

    // routed experts: batched over blockIdx.z = expert
    launch_gemm(false, s->n2h, s->wup_h, s->h, TT, 2 * MIDIM, HH,
                HH, HH, 2 * MIDIM,
                0, (long long)(2 * MIDIM) * HH, (long long)TT * 2 * MIDIM, NE,
                1.f, 0, 0,
                s->tok, s->counts, nullptr, nullptr, TT);
    silu_gate_moe_k<<<dim3(TT, NE), 256>>>();
    launch_gemm(false, s->hah, s->wdn_h, s->routed2, TT, HH, MIDIM,
                MIDIM, MIDIM, HH,
                (long long)TT * MIDIM, (long long)HH * MIDIM, 0, NE,
                1.f, 0, 0,
                nullptr, s->counts, s->orow, s->ew, TT);

    // ffn = routed(slot0) + routed(slot1) + shared  (output part 2)
    combine_k<<<4096, 256>>>(s->routed2, s->shared_o, out + (long long)n, n);
}